// round 15
// baseline (speedup 1.0000x reference)
#include <cuda_runtime.h>

// LengthRegulator, fused single kernel, run-pipelined copy:
// ys[b, f, :] = xs[b, i, :] where cum[b,i-1] <= f < cum[b,i], else 0.
//
// 256-thread blocks, 64 frames each. Pair-sum shuffle scan (validated
// R13/R14) -> scatter frame->row map. Copy: each warp owns 8 consecutive
// frames; loads a source row only on row-change, and prefetches the NEXT
// run's row before issuing the current frame's stores (1-deep software
// pipeline), keeping the store stream fed.

#define BATCH   8
#define TIN     512
#define TOUT    4096
#define DIM4    96                  // 384/4 float4 per row
#define FPB     64                  // frames per block
#define THREADS 256                 // 8 warps
#define FPW     8                   // frames per warp

__device__ float4 g_zero[DIM4];     // stays zero (never written)

__global__ __launch_bounds__(THREADS)
void lr_fused(const float4* __restrict__ xs,
              const int* __restrict__ ds,
              float4* __restrict__ out)
{
    __shared__ int s_wsum[8];
    __shared__ int s_map[FPB];

    const int b      = blockIdx.x;
    const int frame0 = blockIdx.y * FPB;
    const int tid    = threadIdx.x;
    const int lane   = tid & 31;
    const int wid    = tid >> 5;

    // ---- pair-sum scan: thread t owns ds rows 2t, 2t+1 ----
    const int2 dd = ((const int2*)(ds + b * TIN))[tid];
    int v = dd.x + dd.y;
#pragma unroll
    for (int off = 1; off < 32; off <<= 1) {
        int n = __shfl_up_sync(0xffffffffu, v, off);
        if (lane >= off) v += n;
    }
    if (lane == 31) s_wsum[wid] = v;
    if (tid < FPB)  s_map[tid] = -1;
    __syncthreads();

    if (wid == 0 && lane < 8) {
        int w = s_wsum[lane];
#pragma unroll
        for (int off = 1; off < 8; off <<= 1) {
            int n = __shfl_up_sync(0x000000ffu, w, off);
            if (lane >= off) w += n;
        }
        s_wsum[lane] = w;
    }
    __syncthreads();

    const int cum1  = v + (wid > 0 ? s_wsum[wid - 1] : 0);
    const int cum0  = cum1 - dd.y;
    const int left0 = cum0 - dd.x;

    const int fend = frame0 + FPB;
    {
        int lo = left0 < frame0 ? frame0 : left0;
        int hi = cum0  > fend   ? fend   : cum0;
        for (int f = lo; f < hi; f++) s_map[f - frame0] = 2 * tid;
        lo = cum0 < frame0 ? frame0 : cum0;
        hi = cum1 > fend   ? fend   : cum1;
        for (int f = lo; f < hi; f++) s_map[f - frame0] = 2 * tid + 1;
    }
    __syncthreads();

    // ---- copy: warp w owns frames [frame0 + w*FPW, +FPW) ----
    const float4* __restrict__ xsb = xs + (size_t)b * TIN * DIM4;
    const int fbase = wid * FPW;
    float4* __restrict__ o =
        out + (size_t)(b * TOUT + frame0 + fbase) * DIM4 + lane;

    // prime: load first frame's row
    int row_cur = s_map[fbase];                    // warp-uniform
    float4 c0, c1, c2;
    {
        const float4* p = (row_cur >= 0) ? (xsb + row_cur * DIM4) : g_zero;
        c0 = p[lane]; c1 = p[lane + 32]; c2 = p[lane + 64];
    }

#pragma unroll
    for (int k = 0; k < FPW; k++) {
        // prefetch next run's row BEFORE this frame's stores
        int  row_next = row_cur;
        bool change   = false;
        float4 n0, n1, n2;
        if (k + 1 < FPW) {
            row_next = s_map[fbase + k + 1];       // warp-uniform
            change   = (row_next != row_cur);
            if (change) {
                const float4* p = (row_next >= 0) ? (xsb + row_next * DIM4)
                                                  : g_zero;
                n0 = p[lane]; n1 = p[lane + 32]; n2 = p[lane + 64];
            }
        }

        __stcs(o + k * DIM4,      c0);             // independent of n*
        __stcs(o + k * DIM4 + 32, c1);
        __stcs(o + k * DIM4 + 64, c2);

        if (change) { c0 = n0; c1 = n1; c2 = n2; }
        row_cur = row_next;
    }
}

extern "C" void kernel_launch(void* const* d_in, const int* in_sizes, int n_in,
                              void* d_out, int out_size)
{
    const float* xs = (const float*)d_in[0];
    const int*   ds = (const int*)d_in[1];
    float*       out = (float*)d_out;

    dim3 grid(BATCH, TOUT / FPB);   // 8 x 64 = 512 blocks
    lr_fused<<<grid, THREADS>>>((const float4*)xs, ds, (float4*)out);
}